// round 15
// baseline (speedup 1.0000x reference)
#include <cuda_runtime.h>
#include <math.h>
#include <stdint.h>

// Problem constants (fixed for this dataset instance)
#define HQ   16
#define HKV  2
#define DIM  128
#define SCALE 0.08838834764831845f   // 1/sqrt(128)
#define MAXS   1536
#define MAXTC  95
#define NKBLK  24                    // S/64
#define WIN    512
#define KPAD 132   // K rows: (gq*4+t4)%32 distinct -> conflict-free QK A-frag
#define VPAD 136   // V rows: (t4*8+gq)%32 distinct -> conflict-free AV A-frag
#define QPAD 132   // Q rows: conflict-free QK B-frag
#define TILEKF (32 * KPAD)
#define TILEVF (32 * VPAD)

// ---------------- device scratch (static, no allocation) ----------------
__device__ float    g_ck [MAXTC * HKV * DIM];
__device__ float    g_cv [MAXTC * HKV * DIM];
__device__ float    g_cmp[MAXS * HQ * DIM];      // compressed-branch output
__device__ unsigned g_sel[HKV * MAXS];           // 24-bit selected-block mask

__device__ __forceinline__ void cp16(void* smem, const void* g) {
    uint32_t a = (uint32_t)__cvta_generic_to_shared(smem);
    asm volatile("cp.async.cg.shared.global [%0], [%1], 16;" :: "r"(a), "l"(g));
}

// tf32 mma m16n8k8: D += A(16x8) * B(8x8). Raw f32 bits as tf32.
#define MMA_TF32(D, A0, A1, A2, A3, B0, B1)                                   \
    asm volatile("mma.sync.aligned.m16n8k8.row.col.f32.tf32.tf32.f32 "        \
        "{%0,%1,%2,%3}, {%4,%5,%6,%7}, {%8,%9}, {%0,%1,%2,%3};"               \
        : "+f"(D[0]), "+f"(D[1]), "+f"(D[2]), "+f"(D[3])                      \
        : "r"(A0), "r"(A1), "r"(A2), "r"(A3), "r"(B0), "r"(B1))

__device__ __forceinline__ float tf32rna(float x) {
    uint32_t r;
    asm("cvt.rna.tf32.f32 %0, %1;" : "=r"(r) : "f"(x));
    return __uint_as_float(r);
}

// =====================================================================
// Kernel A: compressed K/V (proven R10 shape)
// =====================================================================
__global__ __launch_bounds__(512, 2)
void compress_kernel(const float* __restrict__ k, const float* __restrict__ v,
                     const float* __restrict__ Wk, const float* __restrict__ bk,
                     const float* __restrict__ Wv, const float* __restrict__ bv,
                     const float* __restrict__ pek, const float* __restrict__ pev,
                     int S, int Tc)
{
    extern __shared__ float sm[];
    float* xk  = sm;               // [2][4096]
    float* xv  = sm + 2 * 4096;    // [2][4096]
    float* red = sm + 4 * 4096;    // [2][16seg][2tt][32]

    const int h   = blockIdx.y;
    const int t0  = blockIdx.x * 2;
    const int e0  = blockIdx.z * 32;
    const int tid = threadIdx.x;
    const int seg = tid >> 5;
    const int lane = tid & 31;
    const int e   = e0 + lane;

    for (int tt = 0; tt < 2; ++tt) {
        int t = t0 + tt;
        if (t >= Tc) break;
        for (int f = tid; f < 1024; f += 512) {
            int l = f >> 5, d4 = (f & 31) << 2;
            int pos = t * 16 + l;
            const float4 kk = *(const float4*)(k + (pos * HKV + h) * DIM + d4);
            const float4 vv = *(const float4*)(v + (pos * HKV + h) * DIM + d4);
            const float4 pk = *(const float4*)(pek + l * DIM + d4);
            const float4 pv = *(const float4*)(pev + l * DIM + d4);
            float4 ok; ok.x = kk.x + pk.x; ok.y = kk.y + pk.y; ok.z = kk.z + pk.z; ok.w = kk.w + pk.w;
            float4 ov; ov.x = vv.x + pv.x; ov.y = vv.y + pv.y; ov.z = vv.z + pv.z; ov.w = vv.w + pv.w;
            *(float4*)(xk + tt * 4096 + l * DIM + d4) = ok;
            *(float4*)(xv + tt * 4096 + l * DIM + d4) = ov;
        }
    }
    __syncthreads();

    float ak[2] = {0.f, 0.f};
    float av[2] = {0.f, 0.f};
    const int i0 = seg * 256;
#pragma unroll 4
    for (int i = i0; i < i0 + 256; ++i) {
        float wk = Wk[i * DIM + e];
        float wv = Wv[i * DIM + e];
#pragma unroll
        for (int tt = 0; tt < 2; ++tt) {
            ak[tt] += xk[tt * 4096 + i] * wk;
            av[tt] += xv[tt * 4096 + i] * wv;
        }
    }
#pragma unroll
    for (int tt = 0; tt < 2; ++tt) {
        red[((0 * 16 + seg) * 2 + tt) * 32 + lane] = ak[tt];
        red[((1 * 16 + seg) * 2 + tt) * 32 + lane] = av[tt];
    }
    __syncthreads();

    if (tid < 128) {
        int b  = tid >> 6;
        int tt = (tid >> 5) & 1;
        int ee = tid & 31;
        int t  = t0 + tt;
        if (t < Tc) {
            float sv = 0.f;
#pragma unroll
            for (int sg = 0; sg < 16; ++sg)
                sv += red[((b * 16 + sg) * 2 + tt) * 32 + ee];
            if (b == 0) g_ck[(t * HKV + h) * DIM + e0 + ee] = sv + bk[e0 + ee];
            else        g_cv[(t * HKV + h) * DIM + e0 + ee] = sv + bv[e0 + ee];
        }
    }
}

// =====================================================================
// Kernel B: compressed attention + pooled top-k selection
// (R10 structure + unroll pragmas so independent per-t chains pipeline)
// =====================================================================
__global__ __launch_bounds__(256, 4)
void cmpattn_kernel(const float* __restrict__ q, int S, int Tc)
{
    __shared__ float qs[8][DIM];
    __shared__ float cl[8][96];
    __shared__ float sc[96];
    __shared__ float pooled[NKBLK];

    const int s    = blockIdx.x;
    const int hkv  = blockIdx.y;
    const int tid  = threadIdx.x;
    const int g    = tid >> 5;
    const int lane = tid & 31;

    for (int i = tid; i < 8 * DIM; i += 256) {
        int gg = i >> 7, d = i & 127;
        qs[gg][d] = q[(s * HQ + hkv * 8 + gg) * DIM + d];
    }
    __syncthreads();

    int tvis = (s >= 31) ? ((s - 31) / 16 + 1) : 0;
    if (tvis > Tc) tvis = Tc;

    float q0 = qs[g][lane], q1 = qs[g][lane + 32];
    float q2 = qs[g][lane + 64], q3 = qs[g][lane + 96];

#pragma unroll 4
    for (int t = 0; t < tvis; ++t) {
        const float* ckp = &g_ck[(t * HKV + hkv) * DIM];
        float p = q0 * ckp[lane] + q1 * ckp[lane + 32] +
                  q2 * ckp[lane + 64] + q3 * ckp[lane + 96];
#pragma unroll
        for (int o = 16; o; o >>= 1) p += __shfl_xor_sync(0xffffffffu, p, o);
        if (lane == 0) cl[g][t] = p * SCALE;
    }
    __syncwarp();

    float ssum = 0.f;
    for (int t = lane; t < tvis; t += 32) { float e_ = __expf(cl[g][t]); cl[g][t] = e_; ssum += e_; }
#pragma unroll
    for (int o = 16; o; o >>= 1) ssum += __shfl_xor_sync(0xffffffffu, ssum, o);
    float inv = 1.0f / fmaxf(ssum, 1e-9f);
    for (int t = lane; t < tvis; t += 32) cl[g][t] *= inv;
    for (int t = tvis + lane; t < 96; t += 32) cl[g][t] = 0.f;
    __syncwarp();

    float a0 = 0.f, a1 = 0.f, a2 = 0.f, a3 = 0.f;
#pragma unroll 4
    for (int t = 0; t < tvis; ++t) {
        float p = cl[g][t];
        const float* cvp = &g_cv[(t * HKV + hkv) * DIM];
        a0 += p * cvp[lane];      a1 += p * cvp[lane + 32];
        a2 += p * cvp[lane + 64]; a3 += p * cvp[lane + 96];
    }
    float* outp = &g_cmp[(s * HQ + hkv * 8 + g) * DIM];
    outp[lane] = a0; outp[lane + 32] = a1; outp[lane + 64] = a2; outp[lane + 96] = a3;
    __syncthreads();

    for (int t = tid; t < Tc; t += 256) {
        float sv = 0.f;
#pragma unroll
        for (int gg = 0; gg < 8; ++gg) sv += cl[gg][t];
        sc[t] = sv;
    }
    __syncthreads();

    if (tid < NKBLK) {
        float sum = 0.f; int cnt = 0;
#pragma unroll
        for (int j = 0; j < 5; ++j) {
            int idx = tid * 4 + j;
            if (idx < Tc) { sum += sc[idx]; cnt++; }
        }
        pooled[tid] = sum / (float)cnt;
    }
    __syncthreads();

    if (tid < 32) {
        unsigned selbit = 0;
        if (tid < NKBLK) {
            float vme = pooled[tid];
            int rank = 0;
#pragma unroll
            for (int o = 0; o < NKBLK; ++o) {
                float vo = pooled[o];
                if (vo > vme || (vo == vme && o < tid)) rank++;
            }
            selbit = (rank < 16) ? 1u : 0u;
        }
        unsigned msk = __ballot_sync(0xffffffffu, selbit);
        if (tid == 0) g_sel[hkv * S + s] = msk;
    }
}

// AV via tf32 mma: out^T(dims x queries) += V^T(dims x keys) * P(keys x queries)
#define AV_MMA(PB, ACC)                                                       \
    _Pragma("unroll")                                                         \
    for (int kc = 0; kc < 4; ++kc) {                                          \
        const int k0 = kc * 8;                                                \
        uint32_t b0 = __float_as_uint(PB[(k0 + t4) * 8 + gq]);                \
        uint32_t b1 = __float_as_uint(PB[(k0 + t4 + 4) * 8 + gq]);            \
        _Pragma("unroll")                                                     \
        for (int mt = 0; mt < 4; ++mt) {                                      \
            const int db = dh + mt * 16;                                      \
            uint32_t a0 = __float_as_uint(vs[(k0 + t4) * VPAD + db + gq]);    \
            uint32_t a1 = __float_as_uint(vs[(k0 + t4) * VPAD + db + gq + 8]);\
            uint32_t a2 = __float_as_uint(vs[(k0 + t4 + 4) * VPAD + db + gq]);\
            uint32_t a3 = __float_as_uint(vs[(k0 + t4 + 4) * VPAD + db + gq + 8]);\
            MMA_TF32(ACC[mt], a0, a1, a2, a3, b0, b1);                        \
        }                                                                     \
    }

// denominator partials (warp A only; lane = key)
#define DEN(SRC, SUM)                                                         \
    {                                                                         \
        float4 pa = *(const float4*)((SRC) + lane * 8);                       \
        float4 pb = *(const float4*)((SRC) + lane * 8 + 4);                   \
        SUM[0] += pa.x; SUM[1] += pa.y; SUM[2] += pa.z; SUM[3] += pa.w;       \
        SUM[4] += pb.x; SUM[5] += pb.y; SUM[6] += pb.z; SUM[7] += pb.w;       \
    }

// =====================================================================
// Kernel C: full-mma block-sparse + sliding-window attention.
// R14 + QK mma split into 2 independent accumulator chains (depth 16->8).
// grid ((S/64)*HQ), block 512
// =====================================================================
__global__ __launch_bounds__(512, 1)
void mainattn_kernel(const float* __restrict__ q, const float* __restrict__ k,
                     const float* __restrict__ v, const float* __restrict__ Wg,
                     const float* __restrict__ bg, float* __restrict__ out, int S)
{
    extern __shared__ float sm[];
    float*    qs   = sm;                       // 64*QPAD
    float*    ksb  = qs + 64 * QPAD;           // 2 x 32*KPAD
    float*    vsb  = ksb + 2 * TILEKF;         // 2 x 32*VPAD
    float*    psT  = vsb + 2 * TILEVF;         // 8 groups x 32 keys x 8 queries
    float*    psT2 = psT + 2048;               // W-stream for mixed tiles
    float*    gsm  = psT2 + 2048;              // 64 x 3 gates
    float*    vsm  = gsm + 192;                // 64 x 2 inv denominators
    unsigned* selm = (unsigned*)(vsm + 128);   // 64 + 1(union)

    const int nqt   = gridDim.x / HQ;
    const int qtile = (nqt - 1) - (blockIdx.x / HQ);
    const int h     = blockIdx.x % HQ;
    const int hkv   = h >> 3;
    const int qbase = qtile * 64;
    const int tid   = threadIdx.x;
    const int w     = tid >> 5;
    const int lane  = tid & 31;
    const int g     = w >> 1;                  // pair id 0..7 (8 queries each)
    const int isA   = !(w & 1);
    const int dh    = (w & 1) * 64;            // this warp's dim half
    const int kwb   = (w & 1) * 16;            // this warp's QK key base
    const int gq    = lane >> 2;               // mma groupID
    const int t4    = lane & 3;

    for (int f = tid; f < 2048; f += 512) {
        int ql = f >> 5, d4 = (f & 31) << 2;
        *(float4*)(qs + ql * QPAD + d4) =
            *(const float4*)(q + ((qbase + ql) * HQ + h) * DIM + d4);
    }
    if (tid < 64) selm[tid] = g_sel[hkv * S + qbase + tid];
    __syncthreads();
    if (tid == 0) {
        unsigned u = 0;
#pragma unroll 8
        for (int i = 0; i < 64; ++i) u |= selm[i];
        selm[64] = u;
    }
    __syncthreads();
    const unsigned unionmask = selm[64];

    const int sq0 = qbase + g * 8;       // first query of this pair's group
    const int sj7 = sq0 + 7;
    const int winloCTA = qbase - (WIN - 1);

    float sumS[8], sumW[8];
    float accC[4][4], accSo[4][4], accWo[4][4];
#pragma unroll
    for (int j = 0; j < 8; ++j) { sumS[j] = 0.f; sumW[j] = 0.f; }
#pragma unroll
    for (int mt = 0; mt < 4; ++mt)
#pragma unroll
        for (int r = 0; r < 4; ++r) { accC[mt][r] = 0.f; accSo[mt][r] = 0.f; accWo[mt][r] = 0.f; }

    float* pwg  = psT  + g * 256;
    float* pwg2 = psT2 + g * 256;
    const float* qb = qs + (g * 8) * QPAD;

    const int nkt = (qbase + 64) >> 5;
    int cur = -1;
    for (int t = 0; t < nkt; ++t) {
        int u0t = t << 5;
        if (((unionmask >> (u0t >> 6)) & 1u) || (u0t + 31 >= winloCTA)) { cur = t; break; }
    }
    int buf = 0;
    if (cur >= 0) {
        const int u0 = cur << 5;
        for (int f = tid; f < 1024; f += 512) {
            int u = f >> 5, d4 = (f & 31) << 2;
            int gk = ((u0 + u) * HKV + hkv) * DIM + d4;
            cp16(ksb + u * KPAD + d4, k + gk);
            cp16(vsb + u * VPAD + d4, v + gk);
        }
        asm volatile("cp.async.commit_group;" ::: "memory");
    }

    while (cur >= 0) {
        int nxt = -1;
        for (int t = cur + 1; t < nkt; ++t) {
            int u0t = t << 5;
            if (((unionmask >> (u0t >> 6)) & 1u) || (u0t + 31 >= winloCTA)) { nxt = t; break; }
        }
        asm volatile("cp.async.wait_group 0;" ::: "memory");
        __syncthreads();

        if (nxt >= 0) {
            const int u0n = nxt << 5;
            float* kd = ksb + (buf ^ 1) * TILEKF;
            float* vd = vsb + (buf ^ 1) * TILEVF;
            for (int f = tid; f < 1024; f += 512) {
                int u = f >> 5, d4 = (f & 31) << 2;
                int gk = ((u0n + u) * HKV + hkv) * DIM + d4;
                cp16(kd + u * KPAD + d4, k + gk);
                cp16(vd + u * VPAD + d4, v + gk);
            }
            asm volatile("cp.async.commit_group;" ::: "memory");
        }

        const float* ks = ksb + buf * TILEKF;
        const float* vs = vsb + buf * TILEVF;
        const int u0 = cur << 5;

        if (u0 <= sj7) {
            const int kb = u0 >> 6;
            unsigned sb = 0;
#pragma unroll
            for (int j = 0; j < 8; ++j)
                sb |= ((selm[g * 8 + j] >> kb) & 1u) << j;
            const bool selAll = (sb == 0xFFu);
            const bool selAny = (sb != 0u);
            const bool causalAll  = (u0 + 31 <= sq0);
            const bool fullWinAll = (u0 >= sj7 - (WIN - 1));
            const bool noWinAll   = (u0 + 31 < sq0 - (WIN - 1));

            int mode;
            if (causalAll && selAll && fullWinAll)       mode = 0;   // BOTH
            else if (causalAll && selAll && noWinAll)    mode = 1;   // SEL
            else if (causalAll && !selAny && fullWinAll) mode = 2;   // WIN
            else if (causalAll && !selAny && noWinAll)   mode = -1;  // nothing
            else                                         mode = 3;   // mixed

            if (mode >= 0) {
                // ---- QK mma: 2 independent accumulator chains (ILP) ----
                float dA[4] = {0.f, 0.f, 0.f, 0.f};
                float dB[4] = {0.f, 0.f, 0.f, 0.f};
#pragma unroll
                for (int kk = 0; kk < 16; kk += 2) {
                    {
                        int dim = kk * 8 + t4;
                        uint32_t b0 = __float_as_uint(qb[gq * QPAD + dim]);
                        uint32_t b1 = __float_as_uint(qb[gq * QPAD + dim + 4]);
                        uint32_t a0 = __float_as_uint(ks[(kwb + gq) * KPAD + dim]);
                        uint32_t a1 = __float_as_uint(ks[(kwb + gq + 8) * KPAD + dim]);
                        uint32_t a2 = __float_as_uint(ks[(kwb + gq) * KPAD + dim + 4]);
                        uint32_t a3 = __float_as_uint(ks[(kwb + gq + 8) * KPAD + dim + 4]);
                        MMA_TF32(dA, a0, a1, a2, a3, b0, b1);
                    }
                    {
                        int dim = (kk + 1) * 8 + t4;
                        uint32_t b0 = __float_as_uint(qb[gq * QPAD + dim]);
                        uint32_t b1 = __float_as_uint(qb[gq * QPAD + dim + 4]);
                        uint32_t a0 = __float_as_uint(ks[(kwb + gq) * KPAD + dim]);
                        uint32_t a1 = __float_as_uint(ks[(kwb + gq + 8) * KPAD + dim]);
                        uint32_t a2 = __float_as_uint(ks[(kwb + gq) * KPAD + dim + 4]);
                        uint32_t a3 = __float_as_uint(ks[(kwb + gq + 8) * KPAD + dim + 4]);
                        MMA_TF32(dB, a0, a1, a2, a3, b0, b1);
                    }
                }
                float d[4];
#pragma unroll
                for (int r = 0; r < 4; ++r) d[r] = dA[r] + dB[r];

                float e0 = tf32rna(__expf(d[0] * SCALE));
                float e1 = tf32rna(__expf(d[1] * SCALE));
                float e2 = tf32rna(__expf(d[2] * SCALE));
                float e3 = tf32rna(__expf(d[3] * SCALE));

                if (mode == 3) {
                    int ku0 = u0 + kwb + gq;
                    int ku1 = ku0 + 8;
                    int jqa = sq0 + 2 * t4;
                    int jqb = jqa + 1;
                    bool sela = (sb >> (2 * t4)) & 1u;
                    bool selb = (sb >> (2 * t4 + 1)) & 1u;
                    float2 s0, s1, w0, w1;
                    s0.x = (ku0 <= jqa && sela) ? e0 : 0.f;
                    s0.y = (ku0 <= jqb && selb) ? e1 : 0.f;
                    s1.x = (ku1 <= jqa && sela) ? e2 : 0.f;
                    s1.y = (ku1 <= jqb && selb) ? e3 : 0.f;
                    w0.x = (ku0 <= jqa && ku0 >= jqa - (WIN - 1)) ? e0 : 0.f;
                    w0.y = (ku0 <= jqb && ku0 >= jqb - (WIN - 1)) ? e1 : 0.f;
                    w1.x = (ku1 <= jqa && ku1 >= jqa - (WIN - 1)) ? e2 : 0.f;
                    w1.y = (ku1 <= jqb && ku1 >= jqb - (WIN - 1)) ? e3 : 0.f;
                    *(float2*)(pwg  + (kwb + gq) * 8 + 2 * t4)     = s0;
                    *(float2*)(pwg  + (kwb + gq + 8) * 8 + 2 * t4) = s1;
                    *(float2*)(pwg2 + (kwb + gq) * 8 + 2 * t4)     = w0;
                    *(float2*)(pwg2 + (kwb + gq + 8) * 8 + 2 * t4) = w1;
                } else {
                    float2 p0; p0.x = e0; p0.y = e1;
                    float2 p1; p1.x = e2; p1.y = e3;
                    *(float2*)(pwg + (kwb + gq) * 8 + 2 * t4)     = p0;
                    *(float2*)(pwg + (kwb + gq + 8) * 8 + 2 * t4) = p1;
                }
                asm volatile("bar.sync %0, %1;" :: "r"(g + 1), "r"(64) : "memory");

                if (mode == 0) {
                    if (isA) { DEN(pwg, sumS) DEN(pwg, sumW) }
                    AV_MMA(pwg, accC)
                } else if (mode == 1) {
                    if (isA) { DEN(pwg, sumS) }
                    AV_MMA(pwg, accSo)
                } else if (mode == 2) {
                    if (isA) { DEN(pwg, sumW) }
                    AV_MMA(pwg, accWo)
                } else {
                    if (isA) { DEN(pwg, sumS) DEN(pwg2, sumW) }
                    AV_MMA(pwg, accSo)
                    AV_MMA(pwg2, accWo)
                }
            }
        }

        cur = nxt; buf ^= 1;
    }

    // ---- epilogue ----
#pragma unroll
    for (int jj = 0; jj < 4; ++jj) {
        int qloc = g * 8 + (w & 1) * 4 + jj;
        const float* qrow = qs + qloc * QPAD;
        float4 q4 = *(const float4*)(qrow + 4 * lane);
        float g0 = q4.x * Wg[(4 * lane + 0) * 3 + 0] + q4.y * Wg[(4 * lane + 1) * 3 + 0]
                 + q4.z * Wg[(4 * lane + 2) * 3 + 0] + q4.w * Wg[(4 * lane + 3) * 3 + 0];
        float g1 = q4.x * Wg[(4 * lane + 0) * 3 + 1] + q4.y * Wg[(4 * lane + 1) * 3 + 1]
                 + q4.z * Wg[(4 * lane + 2) * 3 + 1] + q4.w * Wg[(4 * lane + 3) * 3 + 1];
        float g2 = q4.x * Wg[(4 * lane + 0) * 3 + 2] + q4.y * Wg[(4 * lane + 1) * 3 + 2]
                 + q4.z * Wg[(4 * lane + 2) * 3 + 2] + q4.w * Wg[(4 * lane + 3) * 3 + 2];
#pragma unroll
        for (int o = 16; o; o >>= 1) {
            g0 += __shfl_xor_sync(0xffffffffu, g0, o);
            g1 += __shfl_xor_sync(0xffffffffu, g1, o);
            g2 += __shfl_xor_sync(0xffffffffu, g2, o);
        }
        if (lane == 0) {
            gsm[qloc * 3 + 0] = 1.0f / (1.0f + __expf(-(g0 + bg[0])));
            gsm[qloc * 3 + 1] = 1.0f / (1.0f + __expf(-(g1 + bg[1])));
            gsm[qloc * 3 + 2] = 1.0f / (1.0f + __expf(-(g2 + bg[2])));
        }
    }
    if (isA) {
#pragma unroll
        for (int j = 0; j < 8; ++j) {
            float rs = sumS[j], rw = sumW[j];
#pragma unroll
            for (int o = 16; o; o >>= 1) {
                rs += __shfl_xor_sync(0xffffffffu, rs, o);
                rw += __shfl_xor_sync(0xffffffffu, rw, o);
            }
            if (lane == 0) {
                vsm[(g * 8 + j) * 2 + 0] = 1.0f / fmaxf(rs, 1e-9f);
                vsm[(g * 8 + j) * 2 + 1] = 1.0f / fmaxf(rw, 1e-9f);
            }
        }
    }
    asm volatile("bar.sync %0, %1;" :: "r"(g + 1), "r"(64) : "memory");

    const int qA = g * 8 + 2 * t4, qB = qA + 1;
    const float invSa = vsm[qA * 2 + 0], invWa = vsm[qA * 2 + 1];
    const float invSb = vsm[qB * 2 + 0], invWb = vsm[qB * 2 + 1];
    const float gA0 = gsm[qA * 3 + 0], gA1 = gsm[qA * 3 + 1], gA2 = gsm[qA * 3 + 2];
    const float gB0 = gsm[qB * 3 + 0], gB1 = gsm[qB * 3 + 1], gB2 = gsm[qB * 3 + 2];
    const int sA = qbase + qA, sB = qbase + qB;
    const long oA = (long)(sA * HQ + h) * DIM;
    const long oB = (long)(sB * HQ + h) * DIM;
#pragma unroll
    for (int mt = 0; mt < 4; ++mt) {
        int d0i = dh + mt * 16 + gq;
        int d1i = d0i + 8;
        float aS, aW;
        aS = accC[mt][0] + accSo[mt][0]; aW = accC[mt][0] + accWo[mt][0];
        out[oA + d0i] = gA0 * aS * invSa + gA1 * aW * invWa + gA2 * g_cmp[oA + d0i];
        aS = accC[mt][1] + accSo[mt][1]; aW = accC[mt][1] + accWo[mt][1];
        out[oB + d0i] = gB0 * aS * invSb + gB1 * aW * invWb + gB2 * g_cmp[oB + d0i];
        aS = accC[mt][2] + accSo[mt][2]; aW = accC[mt][2] + accWo[mt][2];
        out[oA + d1i] = gA0 * aS * invSa + gA1 * aW * invWa + gA2 * g_cmp[oA + d1i];
        aS = accC[mt][3] + accSo[mt][3]; aW = accC[mt][3] + accWo[mt][3];
        out[oB + d1i] = gB0 * aS * invSb + gB1 * aW * invWb + gB2 * g_cmp[oB + d1i];
    }
}

// =====================================================================
extern "C" void kernel_launch(void* const* d_in, const int* in_sizes, int n_in,
                              void* d_out, int out_size)
{
    const float* q   = (const float*)d_in[0];
    const float* k   = (const float*)d_in[1];
    const float* v   = (const float*)d_in[2];
    const float* Wk  = (const float*)d_in[3];
    const float* bk  = (const float*)d_in[4];
    const float* Wv  = (const float*)d_in[5];
    const float* bv  = (const float*)d_in[6];
    const float* pek = (const float*)d_in[7];
    const float* pev = (const float*)d_in[8];
    const float* Wg  = (const float*)d_in[9];
    const float* bg  = (const float*)d_in[10];
    float* out = (float*)d_out;

    const int S  = in_sizes[0] / (HQ * DIM);
    const int Tc = (S - 32) / 16 + 1;

    const int smemA = (4 * 4096 + 2 * 16 * 2 * 32) * (int)sizeof(float);   // 73728
    const int smemC = (64 * QPAD + 2 * TILEKF + 2 * TILEVF + 2 * 2048
                       + 192 + 128) * (int)sizeof(float)
                      + 72 * (int)sizeof(unsigned);                        // ~120.3 KB

    cudaFuncSetAttribute(compress_kernel, cudaFuncAttributeMaxDynamicSharedMemorySize, smemA);
    cudaFuncSetAttribute(mainattn_kernel, cudaFuncAttributeMaxDynamicSharedMemorySize, smemC);

    dim3 gA((Tc + 1) / 2, HKV, 4);
    compress_kernel<<<gA, 512, smemA>>>(k, v, Wk, bk, Wv, bv, pek, pev, S, Tc);

    dim3 gB(S, HKV);
    cmpattn_kernel<<<gB, 256>>>(q, S, Tc);

    mainattn_kernel<<<(S / 64) * HQ, 512, smemC>>>(q, k, v, Wg, bg, out, S);
}

// round 16
// speedup vs baseline: 1.1106x; 1.1106x over previous
#include <cuda_runtime.h>
#include <math.h>
#include <stdint.h>

// Problem constants (fixed for this dataset instance)
#define HQ   16
#define HKV  2
#define DIM  128
#define SCALE 0.08838834764831845f   // 1/sqrt(128)
#define MAXS   1536
#define MAXTC  95
#define NKBLK  24                    // S/64
#define WIN    512
#define KPAD 132   // K rows: conflict-free QK A-frag
#define VPAD 136   // V rows: conflict-free AV A-frag
#define QPAD 132   // Q rows: conflict-free QK B-frag
#define TILEKF (32 * KPAD)
#define TILEVF (32 * VPAD)

// ---------------- device scratch (static, no allocation) ----------------
__device__ float    g_ck [MAXTC * HKV * DIM];
__device__ float    g_cv [MAXTC * HKV * DIM];
__device__ float    g_cmp[MAXS * HQ * DIM];      // compressed-branch output
__device__ unsigned g_sel[HKV * MAXS];           // 24-bit selected-block mask

__device__ __forceinline__ void cp16(void* smem, const void* g) {
    uint32_t a = (uint32_t)__cvta_generic_to_shared(smem);
    asm volatile("cp.async.cg.shared.global [%0], [%1], 16;" :: "r"(a), "l"(g));
}

// tf32 mma m16n8k8: D += A(16x8) * B(8x8). Raw f32 bits as tf32.
#define MMA_TF32(D, A0, A1, A2, A3, B0, B1)                                   \
    asm volatile("mma.sync.aligned.m16n8k8.row.col.f32.tf32.tf32.f32 "        \
        "{%0,%1,%2,%3}, {%4,%5,%6,%7}, {%8,%9}, {%0,%1,%2,%3};"               \
        : "+f"(D[0]), "+f"(D[1]), "+f"(D[2]), "+f"(D[3])                      \
        : "r"(A0), "r"(A1), "r"(A2), "r"(A3), "r"(B0), "r"(B1))

__device__ __forceinline__ float tf32rna(float x) {
    uint32_t r;
    asm("cvt.rna.tf32.f32 %0, %1;" : "=r"(r) : "f"(x));
    return __uint_as_float(r);
}

// =====================================================================
// Kernel A: compressed K/V (proven R10 shape)
// =====================================================================
__global__ __launch_bounds__(512, 2)
void compress_kernel(const float* __restrict__ k, const float* __restrict__ v,
                     const float* __restrict__ Wk, const float* __restrict__ bk,
                     const float* __restrict__ Wv, const float* __restrict__ bv,
                     const float* __restrict__ pek, const float* __restrict__ pev,
                     int S, int Tc)
{
    extern __shared__ float sm[];
    float* xk  = sm;               // [2][4096]
    float* xv  = sm + 2 * 4096;    // [2][4096]
    float* red = sm + 4 * 4096;    // [2][16seg][2tt][32]

    const int h   = blockIdx.y;
    const int t0  = blockIdx.x * 2;
    const int e0  = blockIdx.z * 32;
    const int tid = threadIdx.x;
    const int seg = tid >> 5;
    const int lane = tid & 31;
    const int e   = e0 + lane;

    for (int tt = 0; tt < 2; ++tt) {
        int t = t0 + tt;
        if (t >= Tc) break;
        for (int f = tid; f < 1024; f += 512) {
            int l = f >> 5, d4 = (f & 31) << 2;
            int pos = t * 16 + l;
            const float4 kk = *(const float4*)(k + (pos * HKV + h) * DIM + d4);
            const float4 vv = *(const float4*)(v + (pos * HKV + h) * DIM + d4);
            const float4 pk = *(const float4*)(pek + l * DIM + d4);
            const float4 pv = *(const float4*)(pev + l * DIM + d4);
            float4 ok; ok.x = kk.x + pk.x; ok.y = kk.y + pk.y; ok.z = kk.z + pk.z; ok.w = kk.w + pk.w;
            float4 ov; ov.x = vv.x + pv.x; ov.y = vv.y + pv.y; ov.z = vv.z + pv.z; ov.w = vv.w + pv.w;
            *(float4*)(xk + tt * 4096 + l * DIM + d4) = ok;
            *(float4*)(xv + tt * 4096 + l * DIM + d4) = ov;
        }
    }
    __syncthreads();

    float ak[2] = {0.f, 0.f};
    float av[2] = {0.f, 0.f};
    const int i0 = seg * 256;
#pragma unroll 4
    for (int i = i0; i < i0 + 256; ++i) {
        float wk = Wk[i * DIM + e];
        float wv = Wv[i * DIM + e];
#pragma unroll
        for (int tt = 0; tt < 2; ++tt) {
            ak[tt] += xk[tt * 4096 + i] * wk;
            av[tt] += xv[tt * 4096 + i] * wv;
        }
    }
#pragma unroll
    for (int tt = 0; tt < 2; ++tt) {
        red[((0 * 16 + seg) * 2 + tt) * 32 + lane] = ak[tt];
        red[((1 * 16 + seg) * 2 + tt) * 32 + lane] = av[tt];
    }
    __syncthreads();

    if (tid < 128) {
        int b  = tid >> 6;
        int tt = (tid >> 5) & 1;
        int ee = tid & 31;
        int t  = t0 + tt;
        if (t < Tc) {
            float sv = 0.f;
#pragma unroll
            for (int sg = 0; sg < 16; ++sg)
                sv += red[((b * 16 + sg) * 2 + tt) * 32 + ee];
            if (b == 0) g_ck[(t * HKV + h) * DIM + e0 + ee] = sv + bk[e0 + ee];
            else        g_cv[(t * HKV + h) * DIM + e0 + ee] = sv + bv[e0 + ee];
        }
    }
}

// =====================================================================
// Kernel B: compressed attention + pooled top-k selection (proven R10)
// =====================================================================
__global__ __launch_bounds__(256, 4)
void cmpattn_kernel(const float* __restrict__ q, int S, int Tc)
{
    __shared__ float qs[8][DIM];
    __shared__ float cl[8][96];
    __shared__ float sc[96];
    __shared__ float pooled[NKBLK];

    const int s    = blockIdx.x;
    const int hkv  = blockIdx.y;
    const int tid  = threadIdx.x;
    const int g    = tid >> 5;
    const int lane = tid & 31;

    for (int i = tid; i < 8 * DIM; i += 256) {
        int gg = i >> 7, d = i & 127;
        qs[gg][d] = q[(s * HQ + hkv * 8 + gg) * DIM + d];
    }
    __syncthreads();

    int tvis = (s >= 31) ? ((s - 31) / 16 + 1) : 0;
    if (tvis > Tc) tvis = Tc;

    float q0 = qs[g][lane], q1 = qs[g][lane + 32];
    float q2 = qs[g][lane + 64], q3 = qs[g][lane + 96];

    for (int t = 0; t < tvis; ++t) {
        const float* ckp = &g_ck[(t * HKV + hkv) * DIM];
        float p = q0 * ckp[lane] + q1 * ckp[lane + 32] +
                  q2 * ckp[lane + 64] + q3 * ckp[lane + 96];
#pragma unroll
        for (int o = 16; o; o >>= 1) p += __shfl_xor_sync(0xffffffffu, p, o);
        if (lane == 0) cl[g][t] = p * SCALE;
    }
    __syncwarp();

    float ssum = 0.f;
    for (int t = lane; t < tvis; t += 32) { float e_ = __expf(cl[g][t]); cl[g][t] = e_; ssum += e_; }
#pragma unroll
    for (int o = 16; o; o >>= 1) ssum += __shfl_xor_sync(0xffffffffu, ssum, o);
    float inv = 1.0f / fmaxf(ssum, 1e-9f);
    for (int t = lane; t < tvis; t += 32) cl[g][t] *= inv;
    for (int t = tvis + lane; t < 96; t += 32) cl[g][t] = 0.f;
    __syncwarp();

    float a0 = 0.f, a1 = 0.f, a2 = 0.f, a3 = 0.f;
    for (int t = 0; t < tvis; ++t) {
        float p = cl[g][t];
        const float* cvp = &g_cv[(t * HKV + hkv) * DIM];
        a0 += p * cvp[lane];      a1 += p * cvp[lane + 32];
        a2 += p * cvp[lane + 64]; a3 += p * cvp[lane + 96];
    }
    float* outp = &g_cmp[(s * HQ + hkv * 8 + g) * DIM];
    outp[lane] = a0; outp[lane + 32] = a1; outp[lane + 64] = a2; outp[lane + 96] = a3;
    __syncthreads();

    for (int t = tid; t < Tc; t += 256) {
        float sv = 0.f;
#pragma unroll
        for (int gg = 0; gg < 8; ++gg) sv += cl[gg][t];
        sc[t] = sv;
    }
    __syncthreads();

    if (tid < NKBLK) {
        float sum = 0.f; int cnt = 0;
#pragma unroll
        for (int j = 0; j < 5; ++j) {
            int idx = tid * 4 + j;
            if (idx < Tc) { sum += sc[idx]; cnt++; }
        }
        pooled[tid] = sum / (float)cnt;
    }
    __syncthreads();

    if (tid < 32) {
        unsigned selbit = 0;
        if (tid < NKBLK) {
            float vme = pooled[tid];
            int rank = 0;
#pragma unroll
            for (int o = 0; o < NKBLK; ++o) {
                float vo = pooled[o];
                if (vo > vme || (vo == vme && o < tid)) rank++;
            }
            selbit = (rank < 16) ? 1u : 0u;
        }
        unsigned msk = __ballot_sync(0xffffffffu, selbit);
        if (tid == 0) g_sel[hkv * S + s] = msk;
    }
}

// AV via tf32 mma: out^T(dims x queries) += V^T(dims x keys) * P(keys x queries)
#define AV_MMA(PB, ACC)                                                       \
    _Pragma("unroll")                                                         \
    for (int kc = 0; kc < 4; ++kc) {                                          \
        const int k0 = kc * 8;                                                \
        uint32_t b0 = __float_as_uint(PB[(k0 + t4) * 8 + gq]);                \
        uint32_t b1 = __float_as_uint(PB[(k0 + t4 + 4) * 8 + gq]);            \
        _Pragma("unroll")                                                     \
        for (int mt = 0; mt < 4; ++mt) {                                      \
            const int db = dh + mt * 16;                                      \
            uint32_t a0 = __float_as_uint(vs[(k0 + t4) * VPAD + db + gq]);    \
            uint32_t a1 = __float_as_uint(vs[(k0 + t4) * VPAD + db + gq + 8]);\
            uint32_t a2 = __float_as_uint(vs[(k0 + t4 + 4) * VPAD + db + gq]);\
            uint32_t a3 = __float_as_uint(vs[(k0 + t4 + 4) * VPAD + db + gq + 8]);\
            MMA_TF32(ACC[mt], a0, a1, a2, a3, b0, b1);                        \
        }                                                                     \
    }

// denominator partials (warp A only; lane = key)
#define DEN(SRC, SUM)                                                         \
    {                                                                         \
        float4 pa = *(const float4*)((SRC) + lane * 8);                       \
        float4 pb = *(const float4*)((SRC) + lane * 8 + 4);                   \
        SUM[0] += pa.x; SUM[1] += pa.y; SUM[2] += pa.z; SUM[3] += pa.w;       \
        SUM[4] += pb.x; SUM[5] += pb.y; SUM[6] += pb.z; SUM[7] += pb.w;       \
    }

// =====================================================================
// Kernel C: full-mma block-sparse + sliding-window attention (R14)
// + Q B-fragment cached in registers (loop-invariant: 32 LDS/tile saved).
// grid ((S/64)*HQ), block 512
// =====================================================================
__global__ __launch_bounds__(512, 1)
void mainattn_kernel(const float* __restrict__ q, const float* __restrict__ k,
                     const float* __restrict__ v, const float* __restrict__ Wg,
                     const float* __restrict__ bg, float* __restrict__ out, int S)
{
    extern __shared__ float sm[];
    float*    qs   = sm;                       // 64*QPAD
    float*    ksb  = qs + 64 * QPAD;           // 2 x 32*KPAD
    float*    vsb  = ksb + 2 * TILEKF;         // 2 x 32*VPAD
    float*    psT  = vsb + 2 * TILEVF;         // 8 groups x 32 keys x 8 queries
    float*    psT2 = psT + 2048;               // W-stream for mixed tiles
    float*    gsm  = psT2 + 2048;              // 64 x 3 gates
    float*    vsm  = gsm + 192;                // 64 x 2 inv denominators
    unsigned* selm = (unsigned*)(vsm + 128);   // 64 + 1(union)

    const int nqt   = gridDim.x / HQ;
    const int qtile = (nqt - 1) - (blockIdx.x / HQ);
    const int h     = blockIdx.x % HQ;
    const int hkv   = h >> 3;
    const int qbase = qtile * 64;
    const int tid   = threadIdx.x;
    const int w     = tid >> 5;
    const int lane  = tid & 31;
    const int g     = w >> 1;                  // pair id 0..7 (8 queries each)
    const int isA   = !(w & 1);
    const int dh    = (w & 1) * 64;            // this warp's dim half
    const int kwb   = (w & 1) * 16;            // this warp's QK key base
    const int gq    = lane >> 2;               // mma groupID
    const int t4    = lane & 3;

    for (int f = tid; f < 2048; f += 512) {
        int ql = f >> 5, d4 = (f & 31) << 2;
        *(float4*)(qs + ql * QPAD + d4) =
            *(const float4*)(q + ((qbase + ql) * HQ + h) * DIM + d4);
    }
    if (tid < 64) selm[tid] = g_sel[hkv * S + qbase + tid];
    __syncthreads();
    if (tid == 0) {
        unsigned u = 0;
#pragma unroll 8
        for (int i = 0; i < 64; ++i) u |= selm[i];
        selm[64] = u;
    }
    __syncthreads();
    const unsigned unionmask = selm[64];

    // ---- cache the loop-invariant Q B-fragment in registers ----
    const float* qb = qs + (g * 8) * QPAD;
    uint32_t qf0[16], qf1[16];
#pragma unroll
    for (int kk = 0; kk < 16; ++kk) {
        int dim = kk * 8 + t4;
        qf0[kk] = __float_as_uint(qb[gq * QPAD + dim]);
        qf1[kk] = __float_as_uint(qb[gq * QPAD + dim + 4]);
    }

    const int sq0 = qbase + g * 8;       // first query of this pair's group
    const int sj7 = sq0 + 7;
    const int winloCTA = qbase - (WIN - 1);

    float sumS[8], sumW[8];
    float accC[4][4], accSo[4][4], accWo[4][4];
#pragma unroll
    for (int j = 0; j < 8; ++j) { sumS[j] = 0.f; sumW[j] = 0.f; }
#pragma unroll
    for (int mt = 0; mt < 4; ++mt)
#pragma unroll
        for (int r = 0; r < 4; ++r) { accC[mt][r] = 0.f; accSo[mt][r] = 0.f; accWo[mt][r] = 0.f; }

    float* pwg  = psT  + g * 256;
    float* pwg2 = psT2 + g * 256;

    const int nkt = (qbase + 64) >> 5;
    int cur = -1;
    for (int t = 0; t < nkt; ++t) {
        int u0t = t << 5;
        if (((unionmask >> (u0t >> 6)) & 1u) || (u0t + 31 >= winloCTA)) { cur = t; break; }
    }
    int buf = 0;
    if (cur >= 0) {
        const int u0 = cur << 5;
        for (int f = tid; f < 1024; f += 512) {
            int u = f >> 5, d4 = (f & 31) << 2;
            int gk = ((u0 + u) * HKV + hkv) * DIM + d4;
            cp16(ksb + u * KPAD + d4, k + gk);
            cp16(vsb + u * VPAD + d4, v + gk);
        }
        asm volatile("cp.async.commit_group;" ::: "memory");
    }

    while (cur >= 0) {
        int nxt = -1;
        for (int t = cur + 1; t < nkt; ++t) {
            int u0t = t << 5;
            if (((unionmask >> (u0t >> 6)) & 1u) || (u0t + 31 >= winloCTA)) { nxt = t; break; }
        }
        asm volatile("cp.async.wait_group 0;" ::: "memory");
        __syncthreads();

        if (nxt >= 0) {
            const int u0n = nxt << 5;
            float* kd = ksb + (buf ^ 1) * TILEKF;
            float* vd = vsb + (buf ^ 1) * TILEVF;
            for (int f = tid; f < 1024; f += 512) {
                int u = f >> 5, d4 = (f & 31) << 2;
                int gk = ((u0n + u) * HKV + hkv) * DIM + d4;
                cp16(kd + u * KPAD + d4, k + gk);
                cp16(vd + u * VPAD + d4, v + gk);
            }
            asm volatile("cp.async.commit_group;" ::: "memory");
        }

        const float* ks = ksb + buf * TILEKF;
        const float* vs = vsb + buf * TILEVF;
        const int u0 = cur << 5;

        if (u0 <= sj7) {
            const int kb = u0 >> 6;
            unsigned sb = 0;
#pragma unroll
            for (int j = 0; j < 8; ++j)
                sb |= ((selm[g * 8 + j] >> kb) & 1u) << j;
            const bool selAll = (sb == 0xFFu);
            const bool selAny = (sb != 0u);
            const bool causalAll  = (u0 + 31 <= sq0);
            const bool fullWinAll = (u0 >= sj7 - (WIN - 1));
            const bool noWinAll   = (u0 + 31 < sq0 - (WIN - 1));

            int mode;
            if (causalAll && selAll && fullWinAll)       mode = 0;   // BOTH
            else if (causalAll && selAll && noWinAll)    mode = 1;   // SEL
            else if (causalAll && !selAny && fullWinAll) mode = 2;   // WIN
            else if (causalAll && !selAny && noWinAll)   mode = -1;  // nothing
            else                                         mode = 3;   // mixed

            if (mode >= 0) {
                // ---- QK mma: this warp's 16 keys x 8 queries ----
                float d[4] = {0.f, 0.f, 0.f, 0.f};
#pragma unroll
                for (int kk = 0; kk < 16; ++kk) {
                    int dim = kk * 8 + t4;
                    uint32_t a0 = __float_as_uint(ks[(kwb + gq) * KPAD + dim]);
                    uint32_t a1 = __float_as_uint(ks[(kwb + gq + 8) * KPAD + dim]);
                    uint32_t a2 = __float_as_uint(ks[(kwb + gq) * KPAD + dim + 4]);
                    uint32_t a3 = __float_as_uint(ks[(kwb + gq + 8) * KPAD + dim + 4]);
                    MMA_TF32(d, a0, a1, a2, a3, qf0[kk], qf1[kk]);
                }
                float e0 = tf32rna(__expf(d[0] * SCALE));
                float e1 = tf32rna(__expf(d[1] * SCALE));
                float e2 = tf32rna(__expf(d[2] * SCALE));
                float e3 = tf32rna(__expf(d[3] * SCALE));

                if (mode == 3) {
                    int ku0 = u0 + kwb + gq;
                    int ku1 = ku0 + 8;
                    int jqa = sq0 + 2 * t4;
                    int jqb = jqa + 1;
                    bool sela = (sb >> (2 * t4)) & 1u;
                    bool selb = (sb >> (2 * t4 + 1)) & 1u;
                    float2 s0, s1, w0, w1;
                    s0.x = (ku0 <= jqa && sela) ? e0 : 0.f;
                    s0.y = (ku0 <= jqb && selb) ? e1 : 0.f;
                    s1.x = (ku1 <= jqa && sela) ? e2 : 0.f;
                    s1.y = (ku1 <= jqb && selb) ? e3 : 0.f;
                    w0.x = (ku0 <= jqa && ku0 >= jqa - (WIN - 1)) ? e0 : 0.f;
                    w0.y = (ku0 <= jqb && ku0 >= jqb - (WIN - 1)) ? e1 : 0.f;
                    w1.x = (ku1 <= jqa && ku1 >= jqa - (WIN - 1)) ? e2 : 0.f;
                    w1.y = (ku1 <= jqb && ku1 >= jqb - (WIN - 1)) ? e3 : 0.f;
                    *(float2*)(pwg  + (kwb + gq) * 8 + 2 * t4)     = s0;
                    *(float2*)(pwg  + (kwb + gq + 8) * 8 + 2 * t4) = s1;
                    *(float2*)(pwg2 + (kwb + gq) * 8 + 2 * t4)     = w0;
                    *(float2*)(pwg2 + (kwb + gq + 8) * 8 + 2 * t4) = w1;
                } else {
                    float2 p0; p0.x = e0; p0.y = e1;
                    float2 p1; p1.x = e2; p1.y = e3;
                    *(float2*)(pwg + (kwb + gq) * 8 + 2 * t4)     = p0;
                    *(float2*)(pwg + (kwb + gq + 8) * 8 + 2 * t4) = p1;
                }
                asm volatile("bar.sync %0, %1;" :: "r"(g + 1), "r"(64) : "memory");

                if (mode == 0) {
                    if (isA) { DEN(pwg, sumS) DEN(pwg, sumW) }
                    AV_MMA(pwg, accC)
                } else if (mode == 1) {
                    if (isA) { DEN(pwg, sumS) }
                    AV_MMA(pwg, accSo)
                } else if (mode == 2) {
                    if (isA) { DEN(pwg, sumW) }
                    AV_MMA(pwg, accWo)
                } else {
                    if (isA) { DEN(pwg, sumS) DEN(pwg2, sumW) }
                    AV_MMA(pwg, accSo)
                    AV_MMA(pwg2, accWo)
                }
            }
        }

        cur = nxt; buf ^= 1;
    }

    // ---- epilogue ----
#pragma unroll
    for (int jj = 0; jj < 4; ++jj) {
        int qloc = g * 8 + (w & 1) * 4 + jj;
        const float* qrow = qs + qloc * QPAD;
        float4 q4 = *(const float4*)(qrow + 4 * lane);
        float g0 = q4.x * Wg[(4 * lane + 0) * 3 + 0] + q4.y * Wg[(4 * lane + 1) * 3 + 0]
                 + q4.z * Wg[(4 * lane + 2) * 3 + 0] + q4.w * Wg[(4 * lane + 3) * 3 + 0];
        float g1 = q4.x * Wg[(4 * lane + 0) * 3 + 1] + q4.y * Wg[(4 * lane + 1) * 3 + 1]
                 + q4.z * Wg[(4 * lane + 2) * 3 + 1] + q4.w * Wg[(4 * lane + 3) * 3 + 1];
        float g2 = q4.x * Wg[(4 * lane + 0) * 3 + 2] + q4.y * Wg[(4 * lane + 1) * 3 + 2]
                 + q4.z * Wg[(4 * lane + 2) * 3 + 2] + q4.w * Wg[(4 * lane + 3) * 3 + 2];
#pragma unroll
        for (int o = 16; o; o >>= 1) {
            g0 += __shfl_xor_sync(0xffffffffu, g0, o);
            g1 += __shfl_xor_sync(0xffffffffu, g1, o);
            g2 += __shfl_xor_sync(0xffffffffu, g2, o);
        }
        if (lane == 0) {
            gsm[qloc * 3 + 0] = 1.0f / (1.0f + __expf(-(g0 + bg[0])));
            gsm[qloc * 3 + 1] = 1.0f / (1.0f + __expf(-(g1 + bg[1])));
            gsm[qloc * 3 + 2] = 1.0f / (1.0f + __expf(-(g2 + bg[2])));
        }
    }
    if (isA) {
#pragma unroll
        for (int j = 0; j < 8; ++j) {
            float rs = sumS[j], rw = sumW[j];
#pragma unroll
            for (int o = 16; o; o >>= 1) {
                rs += __shfl_xor_sync(0xffffffffu, rs, o);
                rw += __shfl_xor_sync(0xffffffffu, rw, o);
            }
            if (lane == 0) {
                vsm[(g * 8 + j) * 2 + 0] = 1.0f / fmaxf(rs, 1e-9f);
                vsm[(g * 8 + j) * 2 + 1] = 1.0f / fmaxf(rw, 1e-9f);
            }
        }
    }
    asm volatile("bar.sync %0, %1;" :: "r"(g + 1), "r"(64) : "memory");

    const int qA = g * 8 + 2 * t4, qB = qA + 1;
    const float invSa = vsm[qA * 2 + 0], invWa = vsm[qA * 2 + 1];
    const float invSb = vsm[qB * 2 + 0], invWb = vsm[qB * 2 + 1];
    const float gA0 = gsm[qA * 3 + 0], gA1 = gsm[qA * 3 + 1], gA2 = gsm[qA * 3 + 2];
    const float gB0 = gsm[qB * 3 + 0], gB1 = gsm[qB * 3 + 1], gB2 = gsm[qB * 3 + 2];
    const int sA = qbase + qA, sB = qbase + qB;
    const long oA = (long)(sA * HQ + h) * DIM;
    const long oB = (long)(sB * HQ + h) * DIM;
#pragma unroll
    for (int mt = 0; mt < 4; ++mt) {
        int d0i = dh + mt * 16 + gq;
        int d1i = d0i + 8;
        float aS, aW;
        aS = accC[mt][0] + accSo[mt][0]; aW = accC[mt][0] + accWo[mt][0];
        out[oA + d0i] = gA0 * aS * invSa + gA1 * aW * invWa + gA2 * g_cmp[oA + d0i];
        aS = accC[mt][1] + accSo[mt][1]; aW = accC[mt][1] + accWo[mt][1];
        out[oB + d0i] = gB0 * aS * invSb + gB1 * aW * invWb + gB2 * g_cmp[oB + d0i];
        aS = accC[mt][2] + accSo[mt][2]; aW = accC[mt][2] + accWo[mt][2];
        out[oA + d1i] = gA0 * aS * invSa + gA1 * aW * invWa + gA2 * g_cmp[oA + d1i];
        aS = accC[mt][3] + accSo[mt][3]; aW = accC[mt][3] + accWo[mt][3];
        out[oB + d1i] = gB0 * aS * invSb + gB1 * aW * invWb + gB2 * g_cmp[oB + d1i];
    }
}

// =====================================================================
extern "C" void kernel_launch(void* const* d_in, const int* in_sizes, int n_in,
                              void* d_out, int out_size)
{
    const float* q   = (const float*)d_in[0];
    const float* k   = (const float*)d_in[1];
    const float* v   = (const float*)d_in[2];
    const float* Wk  = (const float*)d_in[3];
    const float* bk  = (const float*)d_in[4];
    const float* Wv  = (const float*)d_in[5];
    const float* bv  = (const float*)d_in[6];
    const float* pek = (const float*)d_in[7];
    const float* pev = (const float*)d_in[8];
    const float* Wg  = (const float*)d_in[9];
    const float* bg  = (const float*)d_in[10];
    float* out = (float*)d_out;

    const int S  = in_sizes[0] / (HQ * DIM);
    const int Tc = (S - 32) / 16 + 1;

    const int smemA = (4 * 4096 + 2 * 16 * 2 * 32) * (int)sizeof(float);   // 73728
    const int smemC = (64 * QPAD + 2 * TILEKF + 2 * TILEVF + 2 * 2048
                       + 192 + 128) * (int)sizeof(float)
                      + 72 * (int)sizeof(unsigned);                        // ~120.3 KB

    cudaFuncSetAttribute(compress_kernel, cudaFuncAttributeMaxDynamicSharedMemorySize, smemA);
    cudaFuncSetAttribute(mainattn_kernel, cudaFuncAttributeMaxDynamicSharedMemorySize, smemC);

    dim3 gA((Tc + 1) / 2, HKV, 4);
    compress_kernel<<<gA, 512, smemA>>>(k, v, Wk, bk, Wv, bv, pek, pev, S, Tc);

    dim3 gB(S, HKV);
    cmpattn_kernel<<<gB, 256>>>(q, S, Tc);

    mainattn_kernel<<<(S / 64) * HQ, 512, smemC>>>(q, k, v, Wg, bg, out, S);
}